// round 5
// baseline (speedup 1.0000x reference)
#include <cuda_runtime.h>
#include <cuda_bf16.h>
#include <math.h>

// Problem constants
#define NB   64      // batch N
#define LSEQ 512     // sequence length L
#define HD   1024    // hidden H
#define KSPLIT 8     // k-splits for the recurrence GEMM
#define NBLK 128     // persistent blocks (16 o-tiles x 8 k-slices)

// Scratch for split-K partials: [KSPLIT][NB][HD] = 2 MB
__device__ float g_part[KSPLIT * NB * HD];
// Grid-barrier state (monotonic across replays; invariant g_count == NBLK*g_gen
// after every completed barrier, so replays are self-consistent)
__device__ unsigned g_count;
__device__ unsigned g_gen;

// ---------------------------------------------------------------------------
// Kernel 1: xh[m][o] = sum_h emb[x[m]][h] * Wxh[o][h] + bxh[o] + bhh[o]
// m = n*LSEQ + l; written into d_out. 64x64 tile, 256 thr, 4x4 microtile.
// ---------------------------------------------------------------------------
__global__ __launch_bounds__(256) void xh_kernel(
    const int* __restrict__ x, const float* __restrict__ emb,
    const float* __restrict__ Wxh, const float* __restrict__ bxh,
    const float* __restrict__ bhh, float* __restrict__ out)
{
    __shared__ float As[16][68];
    __shared__ float Bs[16][68];
    __shared__ int   toks[64];

    const int m0 = blockIdx.y * 64;
    const int o0 = blockIdx.x * 64;
    const int tid = threadIdx.x;

    if (tid < 64) toks[tid] = x[m0 + tid];
    __syncthreads();

    const int lr = tid >> 2;
    const int lk = (tid & 3) << 2;
    const int tm = (tid >> 4) << 2;
    const int tn = (tid & 15) << 2;

    float acc[4][4];
    #pragma unroll
    for (int i = 0; i < 4; i++)
        #pragma unroll
        for (int j = 0; j < 4; j++) acc[i][j] = 0.0f;

    const float* Erow = emb + (size_t)toks[lr] * HD + lk;
    const float* Wrow = Wxh + (size_t)(o0 + lr) * HD + lk;

    for (int k0 = 0; k0 < HD; k0 += 16) {
        const float4 a4 = *(const float4*)(Erow + k0);
        const float4 b4 = *(const float4*)(Wrow + k0);
        As[lk + 0][lr] = a4.x; As[lk + 1][lr] = a4.y;
        As[lk + 2][lr] = a4.z; As[lk + 3][lr] = a4.w;
        Bs[lk + 0][lr] = b4.x; Bs[lk + 1][lr] = b4.y;
        Bs[lk + 2][lr] = b4.z; Bs[lk + 3][lr] = b4.w;
        __syncthreads();

        #pragma unroll
        for (int kk = 0; kk < 16; kk++) {
            const float4 av = *(const float4*)&As[kk][tm];
            const float4 bv = *(const float4*)&Bs[kk][tn];
            const float a[4] = {av.x, av.y, av.z, av.w};
            const float b[4] = {bv.x, bv.y, bv.z, bv.w};
            #pragma unroll
            for (int i = 0; i < 4; i++)
                #pragma unroll
                for (int j = 0; j < 4; j++)
                    acc[i][j] = fmaf(a[i], b[j], acc[i][j]);
        }
        __syncthreads();
    }

    float bsum[4];
    #pragma unroll
    for (int j = 0; j < 4; j++)
        bsum[j] = bxh[o0 + tn + j] + bhh[o0 + tn + j];

    #pragma unroll
    for (int i = 0; i < 4; i++) {
        float4 v;
        v.x = acc[i][0] + bsum[0];
        v.y = acc[i][1] + bsum[1];
        v.z = acc[i][2] + bsum[2];
        v.w = acc[i][3] + bsum[3];
        *(float4*)&out[(size_t)(m0 + tm + i) * HD + o0 + tn] = v;
    }
}

// ---------------------------------------------------------------------------
// Software grid barrier. REDG arrival on g_count; block 0 detects completion
// (count is monotonic, target = NBLK * target_gen) and publishes g_gen.
// ---------------------------------------------------------------------------
__device__ __forceinline__ void grid_barrier(int bx, unsigned gen0, unsigned& bar_n)
{
    __syncthreads();
    if (threadIdx.x == 0) {
        __threadfence();
        atomicAdd(&g_count, 1u);          // return unused -> REDG
        bar_n++;
        const unsigned tgen = gen0 + bar_n;
        if (bx == 0) {
            const unsigned tcnt = (unsigned)NBLK * tgen;   // wraps consistently
            while (*(volatile unsigned*)&g_count != tcnt) { }
            __threadfence();
            *(volatile unsigned*)&g_gen = tgen;
        } else {
            while (*(volatile unsigned*)&g_gen != tgen) { }
            __threadfence();
        }
    }
    __syncthreads();
}

// ---------------------------------------------------------------------------
// Kernel 2: persistent recurrence. Block (ot = bx&15, ks = bx>>4) keeps its
// 64-o x 128-k slice of W_hh in smem for all 511 steps. Per step:
//   partial[ks][n][o0..] = h_{t-1}[n][kslice] @ Whh_slice   -> g_part
//   barrier; reduce 8 partials + xh, tanh -> out[n][t][:] in place; barrier.
// ---------------------------------------------------------------------------
__global__ __launch_bounds__(256) void rnn_persistent(
    const float* __restrict__ Whh, float* __restrict__ out)
{
    __shared__ float Bs[128][68];   // Whh slice, [k][o]
    __shared__ float As[16][68];    // h staging, [k][n]

    const int bx = blockIdx.x;
    const int ot = bx & 15;
    const int ks = bx >> 4;
    const int o0 = ot * 64;
    const int kbase = ks * 128;
    const int tid = threadIdx.x;

    // Load Whh slice once: Bs[k][o] = Whh[(o0+o)*HD + kbase+k]
    for (int i = tid; i < 64 * 32; i += 256) {
        const int o  = i >> 5;
        const int kq = (i & 31) << 2;
        const float4 w = *(const float4*)&Whh[(size_t)(o0 + o) * HD + kbase + kq];
        Bs[kq + 0][o] = w.x; Bs[kq + 1][o] = w.y;
        Bs[kq + 2][o] = w.z; Bs[kq + 3][o] = w.w;
    }

    const unsigned gen0 = *(volatile unsigned*)&g_gen;  // stable pre-barrier
    unsigned bar_n = 0;

    const int lr = tid >> 2;
    const int lk = (tid & 3) << 2;
    const int tm = (tid >> 4) << 2;
    const int tn = (tid & 15) << 2;

    // Reduce-element mapping: one float2 per thread, 256 per block
    const int idx2 = bx * 256 + tid;        // 0..32767
    const int rn = idx2 >> 9;               // 512 float2 per hidden row
    const int ro = (idx2 & 511) << 1;

    // --- t = 0: h_0 = tanh(xh_0), no recurrent term ---
    {
        float* p = &out[(size_t)rn * (LSEQ * HD) + ro];
        float2 v = *(float2*)p;
        v.x = tanhf(v.x);
        v.y = tanhf(v.y);
        *(float2*)p = v;
    }
    grid_barrier(bx, gen0, bar_n);

    for (int t = 1; t < LSEQ; t++) {
        // ---- split-K partial GEMM ----
        float acc[4][4];
        #pragma unroll
        for (int i = 0; i < 4; i++)
            #pragma unroll
            for (int j = 0; j < 4; j++) acc[i][j] = 0.0f;

        const float* arow = out + (size_t)lr * (LSEQ * HD)
                                + (size_t)(t - 1) * HD + kbase + lk;

        #pragma unroll 2
        for (int k0 = 0; k0 < 128; k0 += 16) {
            const float4 a4 = *(const float4*)(arow + k0);
            __syncthreads();                  // As free from previous chunk
            As[lk + 0][lr] = a4.x; As[lk + 1][lr] = a4.y;
            As[lk + 2][lr] = a4.z; As[lk + 3][lr] = a4.w;
            __syncthreads();

            #pragma unroll
            for (int kk = 0; kk < 16; kk++) {
                const float4 av = *(const float4*)&As[kk][tm];
                const float4 bv = *(const float4*)&Bs[k0 + kk][tn];
                const float a[4] = {av.x, av.y, av.z, av.w};
                const float b[4] = {bv.x, bv.y, bv.z, bv.w};
                #pragma unroll
                for (int i = 0; i < 4; i++)
                    #pragma unroll
                    for (int j = 0; j < 4; j++)
                        acc[i][j] = fmaf(a[i], b[j], acc[i][j]);
            }
        }

        #pragma unroll
        for (int i = 0; i < 4; i++) {
            float4 v;
            v.x = acc[i][0]; v.y = acc[i][1]; v.z = acc[i][2]; v.w = acc[i][3];
            *(float4*)&g_part[(size_t)(ks * NB + tm + i) * HD + o0 + tn] = v;
        }

        grid_barrier(bx, gen0, bar_n);        // partials visible

        // ---- reduce + tanh (in place over out[:, t, :]) ----
        {
            float2 s = make_float2(0.f, 0.f);
            #pragma unroll
            for (int ksi = 0; ksi < KSPLIT; ksi++) {
                const float2 p = *(const float2*)
                    &g_part[(size_t)(ksi * NB + rn) * HD + ro];
                s.x += p.x; s.y += p.y;
            }
            float* po = &out[(size_t)rn * (LSEQ * HD) + (size_t)t * HD + ro];
            const float2 xh = *(const float2*)po;
            float2 h;
            h.x = tanhf(s.x + xh.x);
            h.y = tanhf(s.y + xh.y);
            *(float2*)po = h;
        }

        grid_barrier(bx, gen0, bar_n);        // h_t visible before next step
    }
}

// ---------------------------------------------------------------------------
// Launch: metadata order is x, emb, W_hh_w, W_hh_b, W_xh_w, W_xh_b.
// Graph: exactly 2 kernel nodes.
// ---------------------------------------------------------------------------
extern "C" void kernel_launch(void* const* d_in, const int* in_sizes, int n_in,
                              void* d_out, int out_size)
{
    const int*   x     = (const int*)  d_in[0];
    const float* emb   = (const float*)d_in[1];
    const float* Whh_w = (const float*)d_in[2];
    const float* Whh_b = (const float*)d_in[3];
    const float* Wxh_w = (const float*)d_in[4];
    const float* Wxh_b = (const float*)d_in[5];
    float* out = (float*)d_out;

    dim3 g1(HD / 64, (NB * LSEQ) / 64);   // (16, 512)
    xh_kernel<<<g1, 256>>>(x, emb, Wxh_w, Wxh_b, Whh_b, out);

    rnn_persistent<<<NBLK, 256>>>(Whh_w, out);
}